// round 1
// baseline (speedup 1.0000x reference)
#include <cuda_runtime.h>
#include <math.h>

// ---------------- problem constants ----------------
#define N_NODES 50000
#define NUM_FEA 213
#define HID1 16
#define HEAD1 12
#define CH1 (HID1*HEAD1)   // 192
#define HID2 8
#define HEAD2 8
#define CH2 (HID2*HEAD2)   // 64
#define E_EDGES 800000
#define E_TOT (E_EDGES + N_NODES)   // 850000 (with self loops)

// ---------------- device scratch (no allocs allowed) ----------------
static __device__ float g_h1[N_NODES*CH1];     // features @ W1
static __device__ float g_x1[N_NODES*CH1];     // elu(gat1 out)
static __device__ float g_h2[N_NODES*CH2];     // x1 @ W2
static __device__ float g_as1[N_NODES*HEAD1];
static __device__ float g_ad1[N_NODES*HEAD1];
static __device__ float g_as2[N_NODES*HEAD2];
static __device__ float g_ad2[N_NODES*HEAD2];
static __device__ int   g_deg[N_NODES];
static __device__ int   g_cur[N_NODES];
static __device__ int   g_tmp[N_NODES];
static __device__ int   g_offs[N_NODES+1];
static __device__ int   g_bsum[64];
static __device__ int   g_srcs[E_TOT];

// ---------------- CSR build ----------------
__global__ void zero_kernel(int n)
{
    int i = blockIdx.x*blockDim.x + threadIdx.x;
    if (i < n) { g_deg[i] = 0; g_cur[i] = 0; }
}

__global__ void count_kernel(const int* __restrict__ dstE, int E, int n)
{
    int i = blockIdx.x*blockDim.x + threadIdx.x;
    int tot = E + n;
    if (i >= tot) return;
    int d = (i < E) ? dstE[i] : (i - E);   // self loops appended
    atomicAdd(&g_deg[d], 1);
}

__global__ void scan1_kernel(int n)
{
    __shared__ int sh[1024];
    int t = threadIdx.x;
    int i = blockIdx.x*1024 + t;
    sh[t] = (i < n) ? g_deg[i] : 0;
    __syncthreads();
    #pragma unroll
    for (int off = 1; off < 1024; off <<= 1) {
        int v = 0;
        if (t >= off) v = sh[t-off];
        __syncthreads();
        sh[t] += v;
        __syncthreads();
    }
    if (i < n) g_tmp[i] = sh[t];
    if (t == 1023) g_bsum[blockIdx.x] = sh[1023];
}

__global__ void scan2_kernel(int nb)
{
    if (threadIdx.x == 0) {
        int r = 0;
        for (int i = 0; i < nb; i++) { int v = g_bsum[i]; g_bsum[i] = r; r += v; }
    }
}

__global__ void scan3_kernel(int n)
{
    int i = blockIdx.x*blockDim.x + threadIdx.x;
    if (i < n) g_offs[i+1] = g_tmp[i] + g_bsum[i >> 10];
    if (i == 0) g_offs[0] = 0;
}

__global__ void scatter_kernel(const int* __restrict__ srcE,
                               const int* __restrict__ dstE, int E, int n)
{
    int i = blockIdx.x*blockDim.x + threadIdx.x;
    int tot = E + n;
    if (i >= tot) return;
    int s, d;
    if (i < E) { s = srcE[i]; d = dstE[i]; }
    else       { s = d = i - E; }
    int pos = g_offs[d] + atomicAdd(&g_cur[d], 1);
    g_srcs[pos] = s;
}

// ---------------- fp32 tiled GEMM: C[M,N] = A[M,K] * B[K,N] ----------------
// BM=128 BN=64 BK=8, 256 threads, each computes 8x4
__global__ void gemm_kernel(const float* __restrict__ A,
                            const float* __restrict__ B,
                            float* __restrict__ C,
                            int M, int N, int K)
{
    const int BM = 128, BN = 64, BK = 8;
    __shared__ float sA[BK][BM + 4];
    __shared__ float sB[BK][BN];

    int tx    = threadIdx.x;            // 0..255
    int tcol  = tx & 15;                // 16 col-threads (x4)
    int trow  = tx >> 4;                // 16 row-threads (x8)
    int rowB  = blockIdx.x * BM;
    int colB  = blockIdx.y * BN;

    float acc[8][4];
    #pragma unroll
    for (int i = 0; i < 8; i++)
        #pragma unroll
        for (int j = 0; j < 4; j++) acc[i][j] = 0.f;

    for (int k0 = 0; k0 < K; k0 += BK) {
        // load A tile (BM x BK), transposed in smem
        #pragma unroll
        for (int idx = tx; idx < BM*BK; idx += 256) {
            int r = idx >> 3, kk = idx & 7;
            int gr = rowB + r, gk = k0 + kk;
            sA[kk][r] = (gr < M && gk < K) ? A[(long)gr*K + gk] : 0.f;
        }
        // load B tile (BK x BN)
        #pragma unroll
        for (int idx = tx; idx < BK*BN; idx += 256) {
            int kk = idx >> 6, c = idx & 63;
            int gk = k0 + kk, gc = colB + c;
            sB[kk][c] = (gk < K && gc < N) ? B[(long)gk*N + gc] : 0.f;
        }
        __syncthreads();
        #pragma unroll
        for (int kk = 0; kk < BK; kk++) {
            float4 a0 = *(const float4*)&sA[kk][trow*8];
            float4 a1 = *(const float4*)&sA[kk][trow*8 + 4];
            float4 b0 = *(const float4*)&sB[kk][tcol*4];
            float a[8] = {a0.x,a0.y,a0.z,a0.w,a1.x,a1.y,a1.z,a1.w};
            float b[4] = {b0.x,b0.y,b0.z,b0.w};
            #pragma unroll
            for (int i = 0; i < 8; i++)
                #pragma unroll
                for (int j = 0; j < 4; j++)
                    acc[i][j] = fmaf(a[i], b[j], acc[i][j]);
        }
        __syncthreads();
    }
    #pragma unroll
    for (int i = 0; i < 8; i++) {
        int gr = rowB + trow*8 + i;
        if (gr >= M) continue;
        #pragma unroll
        for (int j = 0; j < 4; j++) {
            int gc = colB + tcol*4 + j;
            if (gc < N) C[(long)gr*N + gc] = acc[i][j];
        }
    }
}

// ---------------- attention scores a_s[n,h], a_d[n,h] ----------------
template<int H, int C>
__global__ void attn_kernel(const float* __restrict__ h,
                            const float* __restrict__ att_s,
                            const float* __restrict__ att_d,
                            float* __restrict__ as_out,
                            float* __restrict__ ad_out, int N)
{
    int t = blockIdx.x*blockDim.x + threadIdx.x;
    if (t >= N*H) return;
    int hh = t % H;
    const float* hp = h + (long)t * C;       // t = n*H + hh; h row-major [N, H*C]
    const float* sp = att_s + hh*C;
    const float* dp = att_d + hh*C;
    float s = 0.f, d = 0.f;
    #pragma unroll
    for (int c = 0; c < C; c += 4) {
        float4 hv = *(const float4*)&hp[c];
        float4 sv = *(const float4*)&sp[c];
        float4 dv = *(const float4*)&dp[c];
        s = fmaf(hv.x,sv.x, fmaf(hv.y,sv.y, fmaf(hv.z,sv.z, fmaf(hv.w,sv.w, s))));
        d = fmaf(hv.x,dv.x, fmaf(hv.y,dv.y, fmaf(hv.z,dv.z, fmaf(hv.w,dv.w, d))));
    }
    as_out[t] = s;
    ad_out[t] = d;
}

// ---------------- per-dst-node softmax aggregation (one warp / node) ----------
// out[v, ch] = elu( sum_e exp(e)/den * h[src, ch] + bias[ch] )
template<int H, int C>
__global__ void agg_kernel(const float* __restrict__ h,
                           const float* __restrict__ as_in,
                           const float* __restrict__ ad_in,
                           const float* __restrict__ bias,
                           float* __restrict__ out, int N)
{
    constexpr int CH = H*C;
    constexpr int J  = CH/32;
    int warp = (blockIdx.x*blockDim.x + threadIdx.x) >> 5;
    int lane = threadIdx.x & 31;
    if (warp >= N) return;
    const int v = warp;

    float adv = (lane < H) ? ad_in[v*H + lane] : 0.f;
    int b = g_offs[v], e = g_offs[v+1];

    float den = 0.f;
    float acc[J];
    #pragma unroll
    for (int j = 0; j < J; j++) acc[j] = 0.f;

    for (int i = b; i < e; i++) {
        int s = g_srcs[i];
        float ex = 0.f;
        if (lane < H) {
            float ev = as_in[s*H + lane] + adv;
            ev = (ev > 0.f) ? ev : 0.2f*ev;      // leaky_relu
            ex = expf(ev);                        // no max-shift: |e| small, exact same alpha
            den += ex;
        }
        const float* hp = h + (long)s*CH;
        #pragma unroll
        for (int j = 0; j < J; j++) {
            int ch = lane + 32*j;
            float exh = __shfl_sync(0xffffffffu, ex, ch / C);
            acc[j] = fmaf(exh, hp[ch], acc[j]);
        }
    }
    #pragma unroll
    for (int j = 0; j < J; j++) {
        int ch = lane + 32*j;
        float dh = __shfl_sync(0xffffffffu, den, ch / C);
        float o = acc[j]/dh + bias[ch];
        o = (o > 0.f) ? o : expm1f(o);           // elu
        out[(long)v*CH + ch] = o;
    }
}

// ---------------- pair head: sigmoid(concat(x[n1],x[n2]) @ linW + linb) ------
__global__ void pair_kernel(const float* __restrict__ x2,
                            const int* __restrict__ n1,
                            const int* __restrict__ n2,
                            const float* __restrict__ linW,
                            const float* __restrict__ linb,
                            float* __restrict__ y, int P)
{
    int p = blockIdx.x*blockDim.x + threadIdx.x;
    if (p >= P) return;
    const float* a  = x2 + (long)n1[p]*CH2;
    const float* bb = x2 + (long)n2[p]*CH2;
    float y0 = linb[0], y1 = linb[1];
    #pragma unroll
    for (int j = 0; j < CH2; j++) {
        float v = a[j];
        y0 = fmaf(v, linW[j*2],   y0);
        y1 = fmaf(v, linW[j*2+1], y1);
    }
    #pragma unroll
    for (int j = 0; j < CH2; j++) {
        float v = bb[j];
        y0 = fmaf(v, linW[(CH2+j)*2],   y0);
        y1 = fmaf(v, linW[(CH2+j)*2+1], y1);
    }
    y[p*2]   = 1.f/(1.f + expf(-y0));
    y[p*2+1] = 1.f/(1.f + expf(-y1));
}

// ---------------- launch ----------------
extern "C" void kernel_launch(void* const* d_in, const int* in_sizes, int n_in,
                              void* d_out, int out_size)
{
    const float* features = (const float*)d_in[0];
    const int*   eidx     = (const int*)  d_in[1];
    const int*   n1idx    = (const int*)  d_in[2];
    const int*   n2idx    = (const int*)  d_in[3];
    const float* W1       = (const float*)d_in[4];
    const float* attS1    = (const float*)d_in[5];
    const float* attD1    = (const float*)d_in[6];
    const float* b1       = (const float*)d_in[7];
    const float* W2       = (const float*)d_in[8];
    const float* attS2    = (const float*)d_in[9];
    const float* attD2    = (const float*)d_in[10];
    const float* b2       = (const float*)d_in[11];
    const float* linW     = (const float*)d_in[12];
    const float* linb     = (const float*)d_in[13];

    const int N = N_NODES;
    const int E = in_sizes[1] / 2;
    const int P = in_sizes[2];
    const int etot = E + N;
    const int* srcE = eidx;
    const int* dstE = eidx + E;

    float* y_out  = (float*)d_out;          // [P,2]
    float* x2_out = y_out + (long)P*2;      // [N,64]

    // resolve device-global addresses (runtime query; capture-safe)
    float *p_h1, *p_x1, *p_h2, *p_as1, *p_ad1, *p_as2, *p_ad2;
    cudaGetSymbolAddress((void**)&p_h1,  g_h1);
    cudaGetSymbolAddress((void**)&p_x1,  g_x1);
    cudaGetSymbolAddress((void**)&p_h2,  g_h2);
    cudaGetSymbolAddress((void**)&p_as1, g_as1);
    cudaGetSymbolAddress((void**)&p_ad1, g_ad1);
    cudaGetSymbolAddress((void**)&p_as2, g_as2);
    cudaGetSymbolAddress((void**)&p_ad2, g_ad2);

    // ---- CSR build (by dst) ----
    zero_kernel<<<(N+255)/256, 256>>>(N);
    count_kernel<<<(etot+255)/256, 256>>>(dstE, E, N);
    int nb = (N + 1023) / 1024;
    scan1_kernel<<<nb, 1024>>>(N);
    scan2_kernel<<<1, 32>>>(nb);
    scan3_kernel<<<(N+255)/256, 256>>>(N);
    scatter_kernel<<<(etot+255)/256, 256>>>(srcE, dstE, E, N);

    // ---- layer 1 ----
    {
        dim3 grid((N + 127)/128, CH1/64);
        gemm_kernel<<<grid, 256>>>(features, W1, p_h1, N, CH1, NUM_FEA);
    }
    attn_kernel<HEAD1, HID1><<<(N*HEAD1 + 255)/256, 256>>>(p_h1, attS1, attD1, p_as1, p_ad1, N);
    agg_kernel<HEAD1, HID1><<<(N*32 + 255)/256, 256>>>(p_h1, p_as1, p_ad1, b1, p_x1, N);

    // ---- layer 2 ----
    {
        dim3 grid((N + 127)/128, CH2/64);
        gemm_kernel<<<grid, 256>>>(p_x1, W2, p_h2, N, CH2, CH1);
    }
    attn_kernel<HEAD2, HID2><<<(N*HEAD2 + 255)/256, 256>>>(p_h2, attS2, attD2, p_as2, p_ad2, N);
    agg_kernel<HEAD2, HID2><<<(N*32 + 255)/256, 256>>>(p_h2, p_as2, p_ad2, b2, x2_out, N);

    // ---- pair head ----
    pair_kernel<<<(P+255)/256, 256>>>(x2_out, n1idx, n2idx, linW, linb, y_out, P);
}